// round 3
// baseline (speedup 1.0000x reference)
#include <cuda_runtime.h>

#define EPSV 1e-7f
#define MAXB 64
#define DD   256

// Scratch: device globals (no allocation allowed in kernel_launch).
__device__ float g_S[MAXB * DD];
__device__ float g_Z[MAXB];

__global__ void zero_k(int B) {
    int i = blockIdx.x * blockDim.x + threadIdx.x;
    if (i < B * DD) g_S[i] = 0.0f;
    if (i < B)      g_Z[i] = 0.0f;
}

// grid: (B, NSPLIT), block: 256 threads = 8 warps.
// Each warp processes tileRows/8 contiguous rows, unrolled by 2.
// Lane l owns d-columns [4l,4l+3] and [128+4l, 128+4l+3].
__global__ void __launch_bounds__(256) attn_k(
    const float* __restrict__ x, const float* __restrict__ W,
    const float* __restrict__ bv, int T, int tileRows)
{
    const int b    = blockIdx.x;
    const int lane = threadIdx.x & 31;
    const int warp = threadIdx.x >> 5;
    const int rowsPerWarp = tileRows >> 3;
    const int t0   = blockIdx.y * tileRows + warp * rowsPerWarp;

    const float4 w0 = __ldg((const float4*)W + lane);
    const float4 w1 = __ldg((const float4*)W + 32 + lane);

    float acc0=0.f, acc1=0.f, acc2=0.f, acc3=0.f;
    float acc4=0.f, acc5=0.f, acc6=0.f, acc7=0.f;
    float zloc = 0.f;

    const float4* xb = (const float4*)(x) + (size_t)b * T * (DD/4);

    for (int i = 0; i < rowsPerWarp; i += 2) {
        const int t = t0 + i;
        const float4* r0 = xb + (size_t)t * (DD/4);
        const float4* r1 = xb + (size_t)(t + 1) * (DD/4);
        // issue all 4 loads up front for MLP
        float4 a0 = r0[lane];
        float4 a1 = r0[32 + lane];
        float4 c0 = r1[lane];
        float4 c1 = r1[32 + lane];

        float d0;
        d0 = a0.x * w0.x;
        d0 = fmaf(a0.y, w0.y, d0);
        d0 = fmaf(a0.z, w0.z, d0);
        d0 = fmaf(a0.w, w0.w, d0);
        d0 = fmaf(a1.x, w1.x, d0);
        d0 = fmaf(a1.y, w1.y, d0);
        d0 = fmaf(a1.z, w1.z, d0);
        d0 = fmaf(a1.w, w1.w, d0);

        float d1;
        d1 = c0.x * w0.x;
        d1 = fmaf(c0.y, w0.y, d1);
        d1 = fmaf(c0.z, w0.z, d1);
        d1 = fmaf(c0.w, w0.w, d1);
        d1 = fmaf(c1.x, w1.x, d1);
        d1 = fmaf(c1.y, w1.y, d1);
        d1 = fmaf(c1.z, w1.z, d1);
        d1 = fmaf(c1.w, w1.w, d1);

        #pragma unroll
        for (int s = 16; s > 0; s >>= 1) {
            d0 += __shfl_xor_sync(0xffffffffu, d0, s);
            d1 += __shfl_xor_sync(0xffffffffu, d1, s);
        }

        const float e0 = __expf(tanhf(d0 + __ldg(bv + t)));
        const float e1 = __expf(tanhf(d1 + __ldg(bv + t + 1)));
        zloc += e0 + e1;

        acc0 = fmaf(a0.x, e0, acc0);
        acc1 = fmaf(a0.y, e0, acc1);
        acc2 = fmaf(a0.z, e0, acc2);
        acc3 = fmaf(a0.w, e0, acc3);
        acc4 = fmaf(a1.x, e0, acc4);
        acc5 = fmaf(a1.y, e0, acc5);
        acc6 = fmaf(a1.z, e0, acc6);
        acc7 = fmaf(a1.w, e0, acc7);

        acc0 = fmaf(c0.x, e1, acc0);
        acc1 = fmaf(c0.y, e1, acc1);
        acc2 = fmaf(c0.z, e1, acc2);
        acc3 = fmaf(c0.w, e1, acc3);
        acc4 = fmaf(c1.x, e1, acc4);
        acc5 = fmaf(c1.y, e1, acc5);
        acc6 = fmaf(c1.z, e1, acc6);
        acc7 = fmaf(c1.w, e1, acc7);
    }

    // Block-level reduction across 8 warps.
    __shared__ float sacc[8][DD];
    __shared__ float sz[8];
    const int j0 = lane * 4;
    sacc[warp][j0 + 0]       = acc0;
    sacc[warp][j0 + 1]       = acc1;
    sacc[warp][j0 + 2]       = acc2;
    sacc[warp][j0 + 3]       = acc3;
    sacc[warp][128 + j0 + 0] = acc4;
    sacc[warp][128 + j0 + 1] = acc5;
    sacc[warp][128 + j0 + 2] = acc6;
    sacc[warp][128 + j0 + 3] = acc7;
    if (lane == 0) sz[warp] = zloc;
    __syncthreads();

    const int tid = threadIdx.x;
    float s = 0.f;
    #pragma unroll
    for (int w = 0; w < 8; w++) s += sacc[w][tid];
    atomicAdd(&g_S[b * DD + tid], s);
    if (tid == 0) {
        float z = 0.f;
        #pragma unroll
        for (int w = 0; w < 8; w++) z += sz[w];
        atomicAdd(&g_Z[b], z);
    }
}

__global__ void finalize_k(float* __restrict__ out) {
    const int b = blockIdx.x;
    const int d = threadIdx.x;
    out[b * DD + d] = g_S[b * DD + d] / (g_Z[b] + EPSV);
}

extern "C" void kernel_launch(void* const* d_in, const int* in_sizes, int n_in,
                              void* d_out, int out_size) {
    const float* x  = (const float*)d_in[0];
    const float* W  = (const float*)d_in[1];
    const float* bv = (const float*)d_in[2];
    float* out = (float*)d_out;

    const int D = in_sizes[1];            // 256
    const int T = in_sizes[2];            // 4096
    const int B = in_sizes[0] / (T * D);  // 64

    const int NSPLIT = 16;                // T=4096 -> tiles of 256 rows
    const int tileRows = T / NSPLIT;

    zero_k<<<(B * DD + 255) / 256, 256>>>(B);
    dim3 grid(B, NSPLIT);
    attn_k<<<grid, 256>>>(x, W, bv, T, tileRows);
    finalize_k<<<B, DD>>>(out);
}

// round 5
// speedup vs baseline: 1.1983x; 1.1983x over previous
#include <cuda_runtime.h>

#define EPSV   1e-7f
#define BB     64
#define DD     256
#define NSPLIT 32

// Scratch (zero-initialized device globals; no allocations allowed).
__device__ float        g_part[BB * NSPLIT * DD];   // 2 MB partial sums
__device__ float        g_zpart[BB * NSPLIT];       // partial Z
__device__ unsigned int g_cnt[BB];                  // per-batch ticket (self-resetting)

__device__ __forceinline__ float tanh_approx(float v) {
    float r;
    asm("tanh.approx.f32 %0, %1;" : "=f"(r) : "f"(v));
    return r;
}

#define DOT8(d, p0, p1)                \
    do {                               \
        d = (p0).x * w0.x;             \
        d = fmaf((p0).y, w0.y, d);     \
        d = fmaf((p0).z, w0.z, d);     \
        d = fmaf((p0).w, w0.w, d);     \
        d = fmaf((p1).x, w1.x, d);     \
        d = fmaf((p1).y, w1.y, d);     \
        d = fmaf((p1).z, w1.z, d);     \
        d = fmaf((p1).w, w1.w, d);     \
    } while (0)

#define ACC8(e, p0, p1)                \
    do {                               \
        acc0 = fmaf((p0).x, e, acc0);  \
        acc1 = fmaf((p0).y, e, acc1);  \
        acc2 = fmaf((p0).z, e, acc2);  \
        acc3 = fmaf((p0).w, e, acc3);  \
        acc4 = fmaf((p1).x, e, acc4);  \
        acc5 = fmaf((p1).y, e, acc5);  \
        acc6 = fmaf((p1).z, e, acc6);  \
        acc7 = fmaf((p1).w, e, acc7);  \
    } while (0)

// grid: (B, NSPLIT), block: 256 threads = 8 warps.
// Each warp streams tileRows/8 rows, 4 rows per iteration (8 LDG.128 in flight/lane).
__global__ void __launch_bounds__(256) attn_k(
    const float* __restrict__ x, const float* __restrict__ W,
    const float* __restrict__ bv, int T, int tileRows, float* __restrict__ out)
{
    const int b    = blockIdx.x;
    const int sp   = blockIdx.y;
    const int lane = threadIdx.x & 31;
    const int warp = threadIdx.x >> 5;
    const int rowsPerWarp = tileRows >> 3;
    const int t0   = sp * tileRows + warp * rowsPerWarp;

    const float4 w0 = __ldg((const float4*)W + lane);
    const float4 w1 = __ldg((const float4*)W + 32 + lane);

    float acc0=0.f, acc1=0.f, acc2=0.f, acc3=0.f;
    float acc4=0.f, acc5=0.f, acc6=0.f, acc7=0.f;
    float zloc = 0.f;

    const float4* xb = (const float4*)(x) + (size_t)b * T * (DD/4);

    for (int i = 0; i < rowsPerWarp; i += 4) {
        const int t = t0 + i;
        const float4* r = xb + (size_t)t * (DD/4);
        // 8 streaming loads issued up front.
        float4 a0 = __ldcs(r +   0 + lane);
        float4 a1 = __ldcs(r +  32 + lane);
        float4 b0 = __ldcs(r +  64 + lane);
        float4 b1 = __ldcs(r +  96 + lane);
        float4 c0 = __ldcs(r + 128 + lane);
        float4 c1 = __ldcs(r + 160 + lane);
        float4 d0v= __ldcs(r + 192 + lane);
        float4 d1v= __ldcs(r + 224 + lane);

        float s0, s1, s2, s3;
        DOT8(s0, a0, a1);
        DOT8(s1, b0, b1);
        DOT8(s2, c0, c1);
        DOT8(s3, d0v, d1v);

        #pragma unroll
        for (int s = 16; s > 0; s >>= 1) {
            s0 += __shfl_xor_sync(0xffffffffu, s0, s);
            s1 += __shfl_xor_sync(0xffffffffu, s1, s);
            s2 += __shfl_xor_sync(0xffffffffu, s2, s);
            s3 += __shfl_xor_sync(0xffffffffu, s3, s);
        }

        const float e0 = __expf(tanh_approx(s0 + __ldg(bv + t + 0)));
        const float e1 = __expf(tanh_approx(s1 + __ldg(bv + t + 1)));
        const float e2 = __expf(tanh_approx(s2 + __ldg(bv + t + 2)));
        const float e3 = __expf(tanh_approx(s3 + __ldg(bv + t + 3)));
        zloc += (e0 + e1) + (e2 + e3);

        ACC8(e0, a0, a1);
        ACC8(e1, b0, b1);
        ACC8(e2, c0, c1);
        ACC8(e3, d0v, d1v);
    }

    // Block-level reduction across 8 warps.
    __shared__ float sacc[8][DD];
    __shared__ float sz[8];
    __shared__ int   s_last;
    const int j0 = lane * 4;
    sacc[warp][j0 + 0]       = acc0;
    sacc[warp][j0 + 1]       = acc1;
    sacc[warp][j0 + 2]       = acc2;
    sacc[warp][j0 + 3]       = acc3;
    sacc[warp][128 + j0 + 0] = acc4;
    sacc[warp][128 + j0 + 1] = acc5;
    sacc[warp][128 + j0 + 2] = acc6;
    sacc[warp][128 + j0 + 3] = acc7;
    if (lane == 0) sz[warp] = zloc;
    __syncthreads();

    const int tid = threadIdx.x;
    float s = 0.f;
    #pragma unroll
    for (int w = 0; w < 8; w++) s += sacc[w][tid];
    g_part[(b * NSPLIT + sp) * DD + tid] = s;
    if (tid == 0) {
        float z = 0.f;
        #pragma unroll
        for (int w = 0; w < 8; w++) z += sz[w];
        g_zpart[b * NSPLIT + sp] = z;
    }

    // Make partials globally visible, then take a ticket.
    __threadfence();
    __syncthreads();
    if (tid == 0) {
        unsigned int old = atomicAdd(&g_cnt[b], 1u);
        s_last = (old == NSPLIT - 1);
    }
    __syncthreads();

    if (s_last) {
        __threadfence();  // acquire side
        float tot = 0.f;
        #pragma unroll
        for (int s2 = 0; s2 < NSPLIT; s2++)
            tot += g_part[(b * NSPLIT + s2) * DD + tid];
        float z = 0.f;
        #pragma unroll
        for (int s2 = 0; s2 < NSPLIT; s2++)
            z += g_zpart[b * NSPLIT + s2];
        out[b * DD + tid] = tot / (z + EPSV);
        if (tid == 0) g_cnt[b] = 0;  // self-reset for next graph replay
    }
}

extern "C" void kernel_launch(void* const* d_in, const int* in_sizes, int n_in,
                              void* d_out, int out_size) {
    const float* x  = (const float*)d_in[0];
    const float* W  = (const float*)d_in[1];
    const float* bv = (const float*)d_in[2];
    float* out = (float*)d_out;

    const int D = in_sizes[1];            // 256
    const int T = in_sizes[2];            // 4096
    const int B = in_sizes[0] / (T * D);  // 64

    const int tileRows = T / NSPLIT;      // 128
    dim3 grid(B, NSPLIT);
    attn_k<<<grid, 256>>>(x, W, bv, T, tileRows, out);
}